// round 2
// baseline (speedup 1.0000x reference)
#include <cuda_runtime.h>
#include <cuda_bf16.h>
#include <math.h>

#define N_NODES 20000
#define D 8
#define DP1 9
#define M_ROWS (N_NODES * DP1)   // 180000
#define IN_F 64
#define HID 128
#define OUT_F 64
#define NE 100000
#define EPS 1e-5f
#define SPAD 64                  // 256B stride between stat accumulators (L2-slice spread)

// ---------------- scratch (device globals; no allocation allowed) ----------------
__device__ float  g_y1[N_NODES * HID];        // x @ W1            (10.24 MB)
__device__ float  g_pre1[M_ROWS * HID];       // agg1@W1 + b1      (92.16 MB)
__device__ float  g_agg2[N_NODES * HID];      //                   (10.24 MB)
__device__ float  g_pre2[N_NODES * OUT_F];    //                   (5.12 MB)
__device__ float  g_embs[N_NODES * OUT_F];    //                   (5.12 MB)
__device__ float  g_s1[HID * SPAD];
__device__ float  g_q1[HID * SPAD];
__device__ float  g_s2[OUT_F * SPAD];
__device__ float  g_q2[OUT_F * SPAD];
__device__ float  g_scale1[HID], g_shift1[HID];
__device__ float  g_scale2[OUT_F], g_shift2[OUT_F];
__device__ double g_loss;

// ---------------- K0: zero accumulators (graph replay safe) ----------------
__global__ void k_zero() {
    int t = threadIdx.x;
    if (t < HID)   { g_s1[t * SPAD] = 0.f; g_q1[t * SPAD] = 0.f; }
    if (t < OUT_F) { g_s2[t * SPAD] = 0.f; g_q2[t * SPAD] = 0.f; }
    if (t == 0) g_loss = 0.0;
}

// ---------------- K1: y1 = x @ W1   [20000,64] @ [64,128] ----------------
// block: 128 thr, 32 rows/block, thread tile 8 rows x 4 cols
__global__ void k_gemm1(const float* __restrict__ x, const float* __restrict__ W1) {
    __shared__ float sX[32 * IN_F];     // 8 KB
    __shared__ float sW[IN_F * HID];    // 32 KB
    const int tid  = threadIdx.x;
    const int row0 = blockIdx.x * 32;
    for (int i = tid; i < 32 * IN_F; i += 128) sX[i] = x[(size_t)row0 * IN_F + i];
    for (int i = tid; i < IN_F * HID; i += 128) sW[i] = W1[i];
    __syncthreads();
    const int tr = tid >> 5;   // 0..3 -> rows tr*8 ..
    const int tc = tid & 31;   // cols tc*4 ..
    float acc[8][4];
#pragma unroll
    for (int r = 0; r < 8; r++)
#pragma unroll
        for (int c = 0; c < 4; c++) acc[r][c] = 0.f;
#pragma unroll 8
    for (int f = 0; f < IN_F; f++) {
        const float4 w = *(const float4*)&sW[f * HID + tc * 4];
#pragma unroll
        for (int r = 0; r < 8; r++) {
            const float a = sX[(tr * 8 + r) * IN_F + f];
            acc[r][0] = fmaf(a, w.x, acc[r][0]);
            acc[r][1] = fmaf(a, w.y, acc[r][1]);
            acc[r][2] = fmaf(a, w.z, acc[r][2]);
            acc[r][3] = fmaf(a, w.w, acc[r][3]);
        }
    }
#pragma unroll
    for (int r = 0; r < 8; r++) {
        float4 v = make_float4(acc[r][0], acc[r][1], acc[r][2], acc[r][3]);
        *(float4*)&g_y1[(size_t)(row0 + tr * 8 + r) * HID + tc * 4] = v;
    }
}

// ---------------- K2: pre1 = maskedMean(y1 rows) + b1, + BN1 stat partials ----------------
// block: 128 thr = 4 warps; 8 nodes/block; one warp per (node, slot j); float4 lanes
__global__ void k_layer1(const float* __restrict__ node_ts,
                         const int*   __restrict__ nbi,
                         const float* __restrict__ nbt,
                         const float* __restrict__ b1) {
    __shared__ float sS[HID];
    __shared__ float sQ[HID];
    const int tid  = threadIdx.x;
    const int w    = tid >> 5, lane = tid & 31;
    if (tid < HID) { sS[tid] = 0.f; sQ[tid] = 0.f; }
    __syncthreads();
    const float4 bb = *(const float4*)&b1[lane * 4];
    float4 ps = make_float4(0.f, 0.f, 0.f, 0.f);
    float4 pq = make_float4(0.f, 0.f, 0.f, 0.f);
    const int i0 = blockIdx.x * 8;
    for (int ii = 0; ii < 8; ii++) {
        const int   i    = i0 + ii;
        const float ts_i = __ldg(&node_ts[i]);
        for (int j = w; j < DP1; j += 4) {
            int ci; float cts;
            if (j < D) { ci = __ldg(&nbi[i * D + j]); cts = __ldg(&nbt[i * D + j]); }
            else       { ci = i;                       cts = ts_i; }
            // self term (always valid)
            float4 acc = *(const float4*)&g_y1[(size_t)ci * HID + lane * 4];
            int cnt = 1;
#pragma unroll
            for (int k = 0; k < D; k++) {
                const float t = __ldg(&nbt[ci * D + k]);
                if (t <= cts) {                      // uniform across warp
                    const int gi = __ldg(&nbi[ci * D + k]);
                    const float4 yv = *(const float4*)&g_y1[(size_t)gi * HID + lane * 4];
                    acc.x += yv.x; acc.y += yv.y; acc.z += yv.z; acc.w += yv.w;
                    cnt++;
                }
            }
            const float inv = 1.f / (float)cnt;
            float4 o;
            o.x = fmaf(acc.x, inv, bb.x);
            o.y = fmaf(acc.y, inv, bb.y);
            o.z = fmaf(acc.z, inv, bb.z);
            o.w = fmaf(acc.w, inv, bb.w);
            // only rows valid under mask2 are ever read downstream
            if (cts <= ts_i)
                *(float4*)&g_pre1[(size_t)(i * DP1 + j) * HID + lane * 4] = o;
            ps.x += o.x; ps.y += o.y; ps.z += o.z; ps.w += o.w;
            pq.x += o.x * o.x; pq.y += o.y * o.y; pq.z += o.z * o.z; pq.w += o.w * o.w;
        }
    }
    atomicAdd(&sS[lane * 4 + 0], ps.x);
    atomicAdd(&sS[lane * 4 + 1], ps.y);
    atomicAdd(&sS[lane * 4 + 2], ps.z);
    atomicAdd(&sS[lane * 4 + 3], ps.w);
    atomicAdd(&sQ[lane * 4 + 0], pq.x);
    atomicAdd(&sQ[lane * 4 + 1], pq.y);
    atomicAdd(&sQ[lane * 4 + 2], pq.z);
    atomicAdd(&sQ[lane * 4 + 3], pq.w);
    __syncthreads();
    if (tid < HID) {
        atomicAdd(&g_s1[tid * SPAD], sS[tid]);
        atomicAdd(&g_q1[tid * SPAD], sQ[tid]);
    }
}

// ---------------- K stats1: finalize BN1 -> per-col scale/shift ----------------
__global__ void k_stats1(const float* __restrict__ gam, const float* __restrict__ bet) {
    const int h = threadIdx.x;
    const float mean = g_s1[h * SPAD] * (1.f / (float)M_ROWS);
    const float var  = g_q1[h * SPAD] * (1.f / (float)M_ROWS) - mean * mean;
    const float sc   = __ldg(&gam[h]) * rsqrtf(fmaxf(var, 0.f) + EPS);
    g_scale1[h] = sc;
    g_shift1[h] = __ldg(&bet[h]) - mean * sc;
}

// ---------------- K3: agg2 = maskedMean_j relu(bn1(pre1)) ----------------
__global__ void k_agg2(const float* __restrict__ node_ts,
                       const float* __restrict__ nbt) {
    const int h  = threadIdx.x;          // 128
    const float sc = g_scale1[h], sh = g_shift1[h];
    const int i0 = blockIdx.x * 8;
    for (int ii = 0; ii < 8; ii++) {
        const int   i  = i0 + ii;
        const float ts = __ldg(&node_ts[i]);
        float acc = 0.f; int cnt = 0;
#pragma unroll
        for (int j = 0; j < DP1; j++) {
            const bool valid = (j == D) || (__ldg(&nbt[i * D + j]) <= ts);
            if (valid) {                  // uniform across block
                const float v = g_pre1[(size_t)(i * DP1 + j) * HID + h];
                acc += fmaxf(fmaf(v, sc, sh), 0.f);
                cnt++;
            }
        }
        g_agg2[(size_t)i * HID + h] = acc / (float)cnt;
    }
}

// ---------------- K4: pre2 = agg2 @ W2 + b2, + BN2 stat partials ----------------
// block: 128 thr, 16 rows/block, thread tile 2 rows x 4 cols
__global__ void k_gemm2(const float* __restrict__ W2, const float* __restrict__ b2) {
    __shared__ float sA[16 * HID];      // 8 KB
    __shared__ float sW[HID * OUT_F];   // 32 KB
    __shared__ float sS[OUT_F], sQ[OUT_F];
    const int tid  = threadIdx.x;
    const int row0 = blockIdx.x * 16;
    for (int i = tid; i < 16 * HID; i += 128) sA[i] = g_agg2[(size_t)row0 * HID + i];
    for (int i = tid; i < HID * OUT_F; i += 128) sW[i] = W2[i];
    if (tid < OUT_F) { sS[tid] = 0.f; sQ[tid] = 0.f; }
    __syncthreads();
    const int tr = tid >> 4;   // 0..7 -> rows tr*2
    const int tc = tid & 15;   // cols tc*4
    float acc[2][4];
#pragma unroll
    for (int r = 0; r < 2; r++)
#pragma unroll
        for (int c = 0; c < 4; c++) acc[r][c] = 0.f;
#pragma unroll 8
    for (int f = 0; f < HID; f++) {
        const float4 wv = *(const float4*)&sW[f * OUT_F + tc * 4];
#pragma unroll
        for (int r = 0; r < 2; r++) {
            const float a = sA[(tr * 2 + r) * HID + f];
            acc[r][0] = fmaf(a, wv.x, acc[r][0]);
            acc[r][1] = fmaf(a, wv.y, acc[r][1]);
            acc[r][2] = fmaf(a, wv.z, acc[r][2]);
            acc[r][3] = fmaf(a, wv.w, acc[r][3]);
        }
    }
    const float4 bbv = *(const float4*)&b2[tc * 4];
    float ps[4] = {0.f, 0.f, 0.f, 0.f}, pq[4] = {0.f, 0.f, 0.f, 0.f};
#pragma unroll
    for (int r = 0; r < 2; r++) {
        float4 o = make_float4(acc[r][0] + bbv.x, acc[r][1] + bbv.y,
                               acc[r][2] + bbv.z, acc[r][3] + bbv.w);
        *(float4*)&g_pre2[(size_t)(row0 + tr * 2 + r) * OUT_F + tc * 4] = o;
        ps[0] += o.x; ps[1] += o.y; ps[2] += o.z; ps[3] += o.w;
        pq[0] += o.x * o.x; pq[1] += o.y * o.y; pq[2] += o.z * o.z; pq[3] += o.w * o.w;
    }
#pragma unroll
    for (int c = 0; c < 4; c++) {
        atomicAdd(&sS[tc * 4 + c], ps[c]);
        atomicAdd(&sQ[tc * 4 + c], pq[c]);
    }
    __syncthreads();
    if (tid < OUT_F) {
        atomicAdd(&g_s2[tid * SPAD], sS[tid]);
        atomicAdd(&g_q2[tid * SPAD], sQ[tid]);
    }
}

// ---------------- K stats2 ----------------
__global__ void k_stats2(const float* __restrict__ gam, const float* __restrict__ bet) {
    const int h = threadIdx.x;
    const float mean = g_s2[h * SPAD] * (1.f / (float)N_NODES);
    const float var  = g_q2[h * SPAD] * (1.f / (float)N_NODES) - mean * mean;
    const float sc   = __ldg(&gam[h]) * rsqrtf(fmaxf(var, 0.f) + EPS);
    g_scale2[h] = sc;
    g_shift2[h] = __ldg(&bet[h]) - mean * sc;
}

// ---------------- K6: embs = relu(bn2(pre2)) ----------------
__global__ void k_embs() {
    const int idx = blockIdx.x * blockDim.x + threadIdx.x;   // over float4s
    if (idx < N_NODES * OUT_F / 4) {
        const int c0 = (idx & 15) * 4;
        float4 v = *(const float4*)&g_pre2[(size_t)idx * 4];
        v.x = fmaxf(fmaf(v.x, g_scale2[c0 + 0], g_shift2[c0 + 0]), 0.f);
        v.y = fmaxf(fmaf(v.y, g_scale2[c0 + 1], g_shift2[c0 + 1]), 0.f);
        v.z = fmaxf(fmaf(v.z, g_scale2[c0 + 2], g_shift2[c0 + 2]), 0.f);
        v.w = fmaxf(fmaf(v.w, g_scale2[c0 + 3], g_shift2[c0 + 3]), 0.f);
        *(float4*)&g_embs[(size_t)idx * 4] = v;
    }
}

// ---------------- K7: HadNet decoder + BCE loss ----------------
// block: 256 thr = 8 warps, 64 pairs/block (warp per pair, lane = 2 features)
__global__ void k_loss(const int* __restrict__ target, const int* __restrict__ neg,
                       const float* __restrict__ Wd, const float* __restrict__ bd) {
    __shared__ float  sWd[OUT_F];
    __shared__ double sAcc[8];
    const int tid = threadIdx.x, w = tid >> 5, lane = tid & 31;
    if (tid < OUT_F) sWd[tid] = Wd[tid];
    __syncthreads();
    const float bdv = __ldg(&bd[0]);
    double acc = 0.0;
    const int p0 = blockIdx.x * 64;
    for (int it = 0; it < 8; it++) {
        const int p = p0 + it * 8 + w;
        int a, b; float label;
        if (p < NE) { a = __ldg(&target[p]);      b = __ldg(&target[NE + p]); label = 1.f; }
        else        { a = __ldg(&neg[p - NE]);    b = __ldg(&neg[p]);         label = 0.f; }
        const float2 ea = *(const float2*)&g_embs[(size_t)a * OUT_F + lane * 2];
        const float2 eb = *(const float2*)&g_embs[(size_t)b * OUT_F + lane * 2];
        float d = ea.x * eb.x * sWd[lane * 2] + ea.y * eb.y * sWd[lane * 2 + 1];
#pragma unroll
        for (int off = 16; off; off >>= 1) d += __shfl_xor_sync(0xffffffff, d, off);
        if (lane == 0) {
            const float pl   = d + bdv;
            const float term = fmaxf(pl, 0.f) - pl * label + log1pf(expf(-fabsf(pl)));
            acc += (double)term;
        }
    }
    if (lane == 0) sAcc[w] = acc;
    __syncthreads();
    if (tid == 0) {
        double s = 0.0;
#pragma unroll
        for (int k = 0; k < 8; k++) s += sAcc[k];
        atomicAdd(&g_loss, s);
    }
}

// ---------------- K8: finalize ----------------
__global__ void k_final(float* __restrict__ out) {
    out[0] = (float)(g_loss * (1.0 / (2.0 * (double)NE)));
}

// ---------------- launch ----------------
extern "C" void kernel_launch(void* const* d_in, const int* in_sizes, int n_in,
                              void* d_out, int out_size) {
    const float* x       = (const float*)d_in[0];
    const float* node_ts = (const float*)d_in[1];
    const int*   nbi     = (const int*)  d_in[2];
    const float* nbt     = (const float*)d_in[3];
    const int*   target  = (const int*)  d_in[4];
    const int*   neg     = (const int*)  d_in[5];
    const float* W1      = (const float*)d_in[6];
    const float* b1      = (const float*)d_in[7];
    const float* g1      = (const float*)d_in[8];
    const float* be1     = (const float*)d_in[9];
    const float* W2      = (const float*)d_in[10];
    const float* b2      = (const float*)d_in[11];
    const float* g2      = (const float*)d_in[12];
    const float* be2     = (const float*)d_in[13];
    const float* Wd      = (const float*)d_in[14];
    const float* bd      = (const float*)d_in[15];
    float* out = (float*)d_out;

    k_zero  <<<1, 128>>>();
    k_gemm1 <<<N_NODES / 32, 128>>>(x, W1);
    k_layer1<<<N_NODES / 8, 128>>>(node_ts, nbi, nbt, b1);
    k_stats1<<<1, HID>>>(g1, be1);
    k_agg2  <<<N_NODES / 8, 128>>>(node_ts, nbt);
    k_gemm2 <<<N_NODES / 16, 128>>>(W2, b2);
    k_stats2<<<1, OUT_F>>>(g2, be2);
    k_embs  <<<(N_NODES * OUT_F / 4 + 255) / 256, 256>>>();
    k_loss  <<<2 * NE / 64, 256>>>(target, neg, Wd, bd);
    k_final <<<1, 1>>>(out);
}

// round 3
// speedup vs baseline: 1.2292x; 1.2292x over previous
#include <cuda_runtime.h>
#include <cuda_bf16.h>
#include <math.h>

#define N_NODES 20000
#define D 8
#define DP1 9
#define M_ROWS (N_NODES * DP1)   // 180000
#define IN_F 64
#define HID 128
#define OUT_F 64
#define NE 100000
#define EPS 1e-5f
#define SPAD 64                  // 256B stride between stat accumulators
#define CAP 96                   // per-child query bucket capacity (mean 9, P(>96)~0)

// ---------------- scratch (device globals; no allocation allowed) ----------------
__device__ float  g_y1[N_NODES * HID];        // x @ W1            (10.24 MB)
__device__ float  g_pre1[M_ROWS * HID];       // agg1@W1 + b1 (valid rows only)
__device__ float  g_pre2[N_NODES * OUT_F];
__device__ float  g_embs[N_NODES * OUT_F];
__device__ int    g_cnt[N_NODES];             // bucket counters
__device__ float  g_bq[N_NODES * CAP];        // bucketed query cts
__device__ int    g_bm[N_NODES * CAP];        // bucketed out-slot (sign = invalid)
__device__ float  g_s1[HID * SPAD],  g_q1[HID * SPAD];
__device__ float  g_s2[OUT_F * SPAD], g_q2[OUT_F * SPAD];
__device__ double g_loss;
__device__ int    g_done;

// ---------------- K1: y1 = x @ W1  (+ zero all per-replay accumulators) ----------------
// grid 625 x 128 thr; 32 rows/block; thread tile 8 rows x 4 cols
__global__ void k_gemm1(const float* __restrict__ x, const float* __restrict__ W1) {
    __shared__ float sX[32 * IN_F];     // 8 KB
    __shared__ float sW[IN_F * HID];    // 32 KB
    const int tid  = threadIdx.x;
    const int row0 = blockIdx.x * 32;
    // per-replay zeroing, distributed across the grid (625*32 = 20000)
    if (tid < 32) g_cnt[blockIdx.x * 32 + tid] = 0;
    if (blockIdx.x == 0) {
        if (tid < HID)   { g_s1[tid * SPAD] = 0.f; g_q1[tid * SPAD] = 0.f; }
        if (tid < OUT_F) { g_s2[tid * SPAD] = 0.f; g_q2[tid * SPAD] = 0.f; }
        if (tid == 0)    { g_loss = 0.0; g_done = 0; }
    }
    for (int i = tid; i < 32 * IN_F; i += 128) sX[i] = x[(size_t)row0 * IN_F + i];
    for (int i = tid; i < IN_F * HID; i += 128) sW[i] = W1[i];
    __syncthreads();
    const int tr = tid >> 5;
    const int tc = tid & 31;
    float acc[8][4];
#pragma unroll
    for (int r = 0; r < 8; r++)
#pragma unroll
        for (int c = 0; c < 4; c++) acc[r][c] = 0.f;
#pragma unroll 8
    for (int f = 0; f < IN_F; f++) {
        const float4 w = *(const float4*)&sW[f * HID + tc * 4];
#pragma unroll
        for (int r = 0; r < 8; r++) {
            const float a = sX[(tr * 8 + r) * IN_F + f];
            acc[r][0] = fmaf(a, w.x, acc[r][0]);
            acc[r][1] = fmaf(a, w.y, acc[r][1]);
            acc[r][2] = fmaf(a, w.z, acc[r][2]);
            acc[r][3] = fmaf(a, w.w, acc[r][3]);
        }
    }
#pragma unroll
    for (int r = 0; r < 8; r++) {
        float4 v = make_float4(acc[r][0], acc[r][1], acc[r][2], acc[r][3]);
        *(float4*)&g_y1[(size_t)(row0 + tr * 8 + r) * HID + tc * 4] = v;
    }
}

// ---------------- K2: scatter queries into per-child buckets ----------------
// query m = i*9+j: child ci, query-ts cts, validity (mask2) in sign of m
__global__ void k_build(const float* __restrict__ node_ts,
                        const int*   __restrict__ nbi,
                        const float* __restrict__ nbt) {
    const int q = blockIdx.x * blockDim.x + threadIdx.x;
    if (q >= M_ROWS) return;
    const int i = q / DP1;
    const int j = q - i * DP1;
    const float ts_i = __ldg(&node_ts[i]);
    int ci; float cts;
    if (j < D) { ci = __ldg(&nbi[i * D + j]); cts = __ldg(&nbt[i * D + j]); }
    else       { ci = i;                      cts = ts_i; }
    const bool valid = (cts <= ts_i);
    const int slot = atomicAdd(&g_cnt[ci], 1);
    if (slot < CAP) {
        g_bq[ci * CAP + slot] = cts;
        g_bm[ci * CAP + slot] = valid ? q : (q | 0x80000000);
    }
}

// ---------------- K3: per-child worker: register-resident rows, answer queries ----------------
// 4 warps/block, one warp per child node; lane holds float4 of each row
__global__ void k_child(const int*   __restrict__ nbi,
                        const float* __restrict__ nbt,
                        const float* __restrict__ b1) {
    __shared__ float sS[HID];
    __shared__ float sQ[HID];
    const int tid  = threadIdx.x;
    const int w    = tid >> 5, lane = tid & 31;
    if (tid < HID) { sS[tid] = 0.f; sQ[tid] = 0.f; }
    __syncthreads();
    const int c = blockIdx.x * 4 + w;

    float ts[D];
#pragma unroll
    for (int k = 0; k < D; k++) ts[k] = __ldg(&nbt[c * D + k]);

    const float4 self = *(const float4*)&g_y1[(size_t)c * HID + lane * 4];
    float4 row[D];
#pragma unroll
    for (int k = 0; k < D; k++) {
        const int gi = __ldg(&nbi[c * D + k]);
        row[k] = *(const float4*)&g_y1[(size_t)gi * HID + lane * 4];
    }
    const float4 bb = *(const float4*)&b1[lane * 4];

    const int n = min(g_cnt[c], CAP);
    float4 ps = make_float4(0.f, 0.f, 0.f, 0.f);
    float4 pq = make_float4(0.f, 0.f, 0.f, 0.f);
    for (int s = 0; s < n; s++) {
        const float cts = g_bq[c * CAP + s];      // uniform across warp
        const int   me  = g_bm[c * CAP + s];
        float4 acc = self; int cnt = 1;
#pragma unroll
        for (int k = 0; k < D; k++) {
            if (ts[k] <= cts) {                   // uniform branch
                acc.x += row[k].x; acc.y += row[k].y;
                acc.z += row[k].z; acc.w += row[k].w;
                cnt++;
            }
        }
        const float inv = 1.f / (float)cnt;
        float4 o;
        o.x = fmaf(acc.x, inv, bb.x);
        o.y = fmaf(acc.y, inv, bb.y);
        o.z = fmaf(acc.z, inv, bb.z);
        o.w = fmaf(acc.w, inv, bb.w);
        ps.x += o.x; ps.y += o.y; ps.z += o.z; ps.w += o.w;
        pq.x += o.x * o.x; pq.y += o.y * o.y; pq.z += o.z * o.z; pq.w += o.w * o.w;
        if (me >= 0)                              // store only mask2-valid rows
            *(float4*)&g_pre1[(size_t)me * HID + lane * 4] = o;
    }
    atomicAdd(&sS[lane * 4 + 0], ps.x);
    atomicAdd(&sS[lane * 4 + 1], ps.y);
    atomicAdd(&sS[lane * 4 + 2], ps.z);
    atomicAdd(&sS[lane * 4 + 3], ps.w);
    atomicAdd(&sQ[lane * 4 + 0], pq.x);
    atomicAdd(&sQ[lane * 4 + 1], pq.y);
    atomicAdd(&sQ[lane * 4 + 2], pq.z);
    atomicAdd(&sQ[lane * 4 + 3], pq.w);
    __syncthreads();
    if (tid < HID) {
        atomicAdd(&g_s1[tid * SPAD], sS[tid]);
        atomicAdd(&g_q1[tid * SPAD], sQ[tid]);
    }
}

// ---------------- K4: fused agg2 + gemm2 (+ inline BN1 finalize, BN2 partials) ----------------
// 128 thr; 16 nodes/block; stage agg2 rows in smem then 2x4 register-tile GEMM
__global__ void k_aggemm2(const float* __restrict__ node_ts,
                          const float* __restrict__ nbt,
                          const float* __restrict__ g1, const float* __restrict__ be1,
                          const float* __restrict__ W2, const float* __restrict__ b2) {
    __shared__ float sA[16 * HID];      // 8 KB
    __shared__ float sW[HID * OUT_F];   // 32 KB
    __shared__ float sS[OUT_F], sQ[OUT_F];
    const int tid  = threadIdx.x;       // = column h for the agg phase
    const int row0 = blockIdx.x * 16;
    for (int i = tid; i < HID * OUT_F; i += 128) sW[i] = W2[i];
    if (tid < OUT_F) { sS[tid] = 0.f; sQ[tid] = 0.f; }
    // BN1 finalize for this thread's column (cheap, redundant per block)
    const float mean1 = g_s1[tid * SPAD] * (1.f / (float)M_ROWS);
    const float var1  = g_q1[tid * SPAD] * (1.f / (float)M_ROWS) - mean1 * mean1;
    const float sc    = __ldg(&g1[tid]) * rsqrtf(fmaxf(var1, 0.f) + EPS);
    const float sh    = __ldg(&be1[tid]) - mean1 * sc;
    for (int ii = 0; ii < 16; ii++) {
        const int   i  = row0 + ii;
        const float ts = __ldg(&node_ts[i]);
        float acc = 0.f; int cnt = 0;
#pragma unroll
        for (int j = 0; j < DP1; j++) {
            const bool valid = (j == D) || (__ldg(&nbt[i * D + j]) <= ts);
            if (valid) {                  // uniform across block
                const float v = g_pre1[(size_t)(i * DP1 + j) * HID + tid];
                acc += fmaxf(fmaf(v, sc, sh), 0.f);
                cnt++;
            }
        }
        sA[ii * HID + tid] = acc / (float)cnt;
    }
    __syncthreads();
    const int tr = tid >> 4;   // rows tr*2
    const int tc = tid & 15;   // cols tc*4
    float acc[2][4];
#pragma unroll
    for (int r = 0; r < 2; r++)
#pragma unroll
        for (int cc = 0; cc < 4; cc++) acc[r][cc] = 0.f;
#pragma unroll 8
    for (int f = 0; f < HID; f++) {
        const float4 wv = *(const float4*)&sW[f * OUT_F + tc * 4];
#pragma unroll
        for (int r = 0; r < 2; r++) {
            const float a = sA[(tr * 2 + r) * HID + f];
            acc[r][0] = fmaf(a, wv.x, acc[r][0]);
            acc[r][1] = fmaf(a, wv.y, acc[r][1]);
            acc[r][2] = fmaf(a, wv.z, acc[r][2]);
            acc[r][3] = fmaf(a, wv.w, acc[r][3]);
        }
    }
    const float4 bbv = *(const float4*)&b2[tc * 4];
    float ps[4] = {0.f, 0.f, 0.f, 0.f}, pq[4] = {0.f, 0.f, 0.f, 0.f};
#pragma unroll
    for (int r = 0; r < 2; r++) {
        float4 o = make_float4(acc[r][0] + bbv.x, acc[r][1] + bbv.y,
                               acc[r][2] + bbv.z, acc[r][3] + bbv.w);
        *(float4*)&g_pre2[(size_t)(row0 + tr * 2 + r) * OUT_F + tc * 4] = o;
        ps[0] += o.x; ps[1] += o.y; ps[2] += o.z; ps[3] += o.w;
        pq[0] += o.x * o.x; pq[1] += o.y * o.y; pq[2] += o.z * o.z; pq[3] += o.w * o.w;
    }
#pragma unroll
    for (int cc = 0; cc < 4; cc++) {
        atomicAdd(&sS[tc * 4 + cc], ps[cc]);
        atomicAdd(&sQ[tc * 4 + cc], pq[cc]);
    }
    __syncthreads();
    if (tid < OUT_F) {
        atomicAdd(&g_s2[tid * SPAD], sS[tid]);
        atomicAdd(&g_q2[tid * SPAD], sQ[tid]);
    }
}

// ---------------- K5: embs = relu(bn2(pre2)) (BN2 finalize in smem per block) ----------------
__global__ void k_embs(const float* __restrict__ g2, const float* __restrict__ be2) {
    __shared__ float sSc[OUT_F], sSh[OUT_F];
    const int tid = threadIdx.x;
    if (tid < OUT_F) {
        const float mean = g_s2[tid * SPAD] * (1.f / (float)N_NODES);
        const float var  = g_q2[tid * SPAD] * (1.f / (float)N_NODES) - mean * mean;
        const float sc   = __ldg(&g2[tid]) * rsqrtf(fmaxf(var, 0.f) + EPS);
        sSc[tid] = sc;
        sSh[tid] = __ldg(&be2[tid]) - mean * sc;
    }
    __syncthreads();
    const int idx = blockIdx.x * blockDim.x + tid;   // over float4s
    if (idx < N_NODES * OUT_F / 4) {
        const int c0 = (idx & 15) * 4;
        float4 v = *(const float4*)&g_pre2[(size_t)idx * 4];
        v.x = fmaxf(fmaf(v.x, sSc[c0 + 0], sSh[c0 + 0]), 0.f);
        v.y = fmaxf(fmaf(v.y, sSc[c0 + 1], sSh[c0 + 1]), 0.f);
        v.z = fmaxf(fmaf(v.z, sSc[c0 + 2], sSh[c0 + 2]), 0.f);
        v.w = fmaxf(fmaf(v.w, sSc[c0 + 3], sSh[c0 + 3]), 0.f);
        *(float4*)&g_embs[(size_t)idx * 4] = v;
    }
}

// ---------------- K6: decoder + BCE loss (+ last-block finalize) ----------------
// 256 thr = 8 warps; 2 pairs/warp (half-warp float4 dot); 128 pairs/block
__global__ void k_loss(const int* __restrict__ target, const int* __restrict__ neg,
                       const float* __restrict__ Wd, const float* __restrict__ bd,
                       float* __restrict__ out) {
    __shared__ float  sWd[OUT_F];
    __shared__ double sAcc[8];
    const int tid = threadIdx.x, w = tid >> 5, lane = tid & 31;
    const int half = lane >> 4, hl = lane & 15;     // half-warp id, lane-in-half
    if (tid < OUT_F) sWd[tid] = Wd[tid];
    __syncthreads();
    const float bdv = __ldg(&bd[0]);
    const float4 wd = *(const float4*)&sWd[hl * 4];
    double acc = 0.0;
    const int p0 = blockIdx.x * 128;
    for (int it = 0; it < 8; it++) {
        const int p = p0 + it * 16 + w * 2 + half;
        float d = 0.f; float label = 0.f; bool live = (p < 2 * NE);
        if (live) {
            int a, b;
            if (p < NE) { a = __ldg(&target[p]);   b = __ldg(&target[NE + p]); label = 1.f; }
            else        { a = __ldg(&neg[p - NE]); b = __ldg(&neg[p]);         label = 0.f; }
            const float4 ea = *(const float4*)&g_embs[(size_t)a * OUT_F + hl * 4];
            const float4 eb = *(const float4*)&g_embs[(size_t)b * OUT_F + hl * 4];
            d = ea.x * eb.x * wd.x + ea.y * eb.y * wd.y
              + ea.z * eb.z * wd.z + ea.w * eb.w * wd.w;
        }
#pragma unroll
        for (int off = 8; off; off >>= 1) d += __shfl_xor_sync(0xffffffff, d, off);
        if (hl == 0 && live) {
            const float pl   = d + bdv;
            const float term = fmaxf(pl, 0.f) - pl * label + log1pf(expf(-fabsf(pl)));
            acc += (double)term;
        }
    }
    // warp reduce (only hl==0 lanes hold nonzero)
    acc += __shfl_xor_sync(0xffffffff, acc, 16);
    if (lane == 0) sAcc[w] = acc;
    __syncthreads();
    if (tid == 0) {
        double s = 0.0;
#pragma unroll
        for (int k = 0; k < 8; k++) s += sAcc[k];
        atomicAdd(&g_loss, s);
        __threadfence();
        const int dn = atomicAdd(&g_done, 1);
        if (dn == (int)gridDim.x - 1)
            out[0] = (float)(g_loss * (1.0 / (2.0 * (double)NE)));
    }
}

// ---------------- launch ----------------
extern "C" void kernel_launch(void* const* d_in, const int* in_sizes, int n_in,
                              void* d_out, int out_size) {
    const float* x       = (const float*)d_in[0];
    const float* node_ts = (const float*)d_in[1];
    const int*   nbi     = (const int*)  d_in[2];
    const float* nbt     = (const float*)d_in[3];
    const int*   target  = (const int*)  d_in[4];
    const int*   neg     = (const int*)  d_in[5];
    const float* W1      = (const float*)d_in[6];
    const float* b1      = (const float*)d_in[7];
    const float* g1      = (const float*)d_in[8];
    const float* be1     = (const float*)d_in[9];
    const float* W2      = (const float*)d_in[10];
    const float* b2      = (const float*)d_in[11];
    const float* g2      = (const float*)d_in[12];
    const float* be2     = (const float*)d_in[13];
    const float* Wd      = (const float*)d_in[14];
    const float* bd      = (const float*)d_in[15];
    float* out = (float*)d_out;

    k_gemm1  <<<N_NODES / 32, 128>>>(x, W1);
    k_build  <<<(M_ROWS + 255) / 256, 256>>>(node_ts, nbi, nbt);
    k_child  <<<N_NODES / 4, 128>>>(nbi, nbt, b1);
    k_aggemm2<<<N_NODES / 16, 128>>>(node_ts, nbt, g1, be1, W2, b2);
    k_embs   <<<(N_NODES * OUT_F / 4 + 255) / 256, 256>>>(g2, be2);
    k_loss   <<<(2 * NE + 127) / 128, 256>>>(target, neg, Wd, bd, out);
}

// round 5
// speedup vs baseline: 1.3853x; 1.1270x over previous
#include <cuda_runtime.h>
#include <cuda_bf16.h>
#include <math.h>

#define N_NODES 20000
#define D 8
#define DP1 9
#define M_ROWS (N_NODES * DP1)   // 180000
#define IN_F 64
#define HID 128
#define OUT_F 64
#define NE 100000
#define EPS 1e-5f
#define SPAD 64                  // 256B stride between stat accumulators
#define CAP 96                   // per-child query bucket capacity

// ---------------- scratch (device globals; no allocation allowed) ----------------
__device__ float  g_y1[N_NODES * HID];        // x @ W1            (10.24 MB)
__device__ float  g_pre1[M_ROWS * HID];       // agg1@W1 + b1 (valid rows only)
__device__ float  g_agg2[N_NODES * HID];      // (10.24 MB)
__device__ float  g_pre2[N_NODES * OUT_F];    // (5.12 MB)
__device__ int    g_cnt[N_NODES];             // bucket counters
__device__ float  g_bq[N_NODES * CAP];        // bucketed query cts
__device__ int    g_bm[N_NODES * CAP];        // bucketed out-slot (sign = invalid)
__device__ float  g_s1[HID * SPAD],  g_q1[HID * SPAD];
__device__ float  g_s2[OUT_F * SPAD], g_q2[OUT_F * SPAD];
__device__ double g_loss;
__device__ int    g_done;

// ---------------- K1: y1 = x @ W1  (+ zero all per-replay accumulators) ----------------
__global__ void k_gemm1(const float* __restrict__ x, const float* __restrict__ W1) {
    __shared__ float sX[32 * IN_F];     // 8 KB
    __shared__ float sW[IN_F * HID];    // 32 KB
    const int tid  = threadIdx.x;
    const int row0 = blockIdx.x * 32;
    if (tid < 32) g_cnt[blockIdx.x * 32 + tid] = 0;
    if (blockIdx.x == 0) {
        if (tid < HID)   { g_s1[tid * SPAD] = 0.f; g_q1[tid * SPAD] = 0.f; }
        if (tid < OUT_F) { g_s2[tid * SPAD] = 0.f; g_q2[tid * SPAD] = 0.f; }
        if (tid == 0)    { g_loss = 0.0; g_done = 0; }
    }
    for (int i = tid; i < 32 * IN_F; i += 128) sX[i] = x[(size_t)row0 * IN_F + i];
    for (int i = tid; i < IN_F * HID; i += 128) sW[i] = W1[i];
    __syncthreads();
    const int tr = tid >> 5;
    const int tc = tid & 31;
    float acc[8][4];
#pragma unroll
    for (int r = 0; r < 8; r++)
#pragma unroll
        for (int c = 0; c < 4; c++) acc[r][c] = 0.f;
#pragma unroll 8
    for (int f = 0; f < IN_F; f++) {
        const float4 w = *(const float4*)&sW[f * HID + tc * 4];
#pragma unroll
        for (int r = 0; r < 8; r++) {
            const float a = sX[(tr * 8 + r) * IN_F + f];
            acc[r][0] = fmaf(a, w.x, acc[r][0]);
            acc[r][1] = fmaf(a, w.y, acc[r][1]);
            acc[r][2] = fmaf(a, w.z, acc[r][2]);
            acc[r][3] = fmaf(a, w.w, acc[r][3]);
        }
    }
#pragma unroll
    for (int r = 0; r < 8; r++) {
        float4 v = make_float4(acc[r][0], acc[r][1], acc[r][2], acc[r][3]);
        *(float4*)&g_y1[(size_t)(row0 + tr * 8 + r) * HID + tc * 4] = v;
    }
}

// ---------------- K2: scatter queries into per-child buckets ----------------
__global__ void k_build(const float* __restrict__ node_ts,
                        const int*   __restrict__ nbi,
                        const float* __restrict__ nbt) {
    const int q = blockIdx.x * blockDim.x + threadIdx.x;
    if (q >= M_ROWS) return;
    const int i = q / DP1;
    const int j = q - i * DP1;
    const float ts_i = __ldg(&node_ts[i]);
    int ci; float cts;
    if (j < D) { ci = __ldg(&nbi[i * D + j]); cts = __ldg(&nbt[i * D + j]); }
    else       { ci = i;                      cts = ts_i; }
    const bool valid = (cts <= ts_i);
    const int slot = atomicAdd(&g_cnt[ci], 1);
    if (slot < CAP) {
        g_bq[ci * CAP + slot] = cts;
        g_bm[ci * CAP + slot] = valid ? q : (q | 0x80000000);
    }
}

// ---------------- K3: per-child worker: register-resident rows, answer queries ----------------
__global__ void k_child(const int*   __restrict__ nbi,
                        const float* __restrict__ nbt,
                        const float* __restrict__ b1) {
    __shared__ float sS[HID];
    __shared__ float sQ[HID];
    const int tid  = threadIdx.x;
    const int w    = tid >> 5, lane = tid & 31;
    if (tid < HID) { sS[tid] = 0.f; sQ[tid] = 0.f; }
    __syncthreads();
    const int c = blockIdx.x * 4 + w;

    float ts[D];
#pragma unroll
    for (int k = 0; k < D; k++) ts[k] = __ldg(&nbt[c * D + k]);

    const float4 self = *(const float4*)&g_y1[(size_t)c * HID + lane * 4];
    float4 row[D];
#pragma unroll
    for (int k = 0; k < D; k++) {
        const int gi = __ldg(&nbi[c * D + k]);
        row[k] = *(const float4*)&g_y1[(size_t)gi * HID + lane * 4];
    }
    const float4 bb = *(const float4*)&b1[lane * 4];

    const int n = min(g_cnt[c], CAP);
    float4 ps = make_float4(0.f, 0.f, 0.f, 0.f);
    float4 pq = make_float4(0.f, 0.f, 0.f, 0.f);
    for (int s = 0; s < n; s++) {
        const float cts = g_bq[c * CAP + s];      // uniform across warp
        const int   me  = g_bm[c * CAP + s];
        float4 acc = self; int cnt = 1;
#pragma unroll
        for (int k = 0; k < D; k++) {
            if (ts[k] <= cts) {                   // uniform predicate on registers
                acc.x += row[k].x; acc.y += row[k].y;
                acc.z += row[k].z; acc.w += row[k].w;
                cnt++;
            }
        }
        const float inv = 1.f / (float)cnt;
        float4 o;
        o.x = fmaf(acc.x, inv, bb.x);
        o.y = fmaf(acc.y, inv, bb.y);
        o.z = fmaf(acc.z, inv, bb.z);
        o.w = fmaf(acc.w, inv, bb.w);
        ps.x += o.x; ps.y += o.y; ps.z += o.z; ps.w += o.w;
        pq.x += o.x * o.x; pq.y += o.y * o.y; pq.z += o.z * o.z; pq.w += o.w * o.w;
        if (me >= 0)                              // store only mask2-valid rows
            *(float4*)&g_pre1[(size_t)me * HID + lane * 4] = o;
    }
    atomicAdd(&sS[lane * 4 + 0], ps.x);
    atomicAdd(&sS[lane * 4 + 1], ps.y);
    atomicAdd(&sS[lane * 4 + 2], ps.z);
    atomicAdd(&sS[lane * 4 + 3], ps.w);
    atomicAdd(&sQ[lane * 4 + 0], pq.x);
    atomicAdd(&sQ[lane * 4 + 1], pq.y);
    atomicAdd(&sQ[lane * 4 + 2], pq.z);
    atomicAdd(&sQ[lane * 4 + 3], pq.w);
    __syncthreads();
    if (tid < HID) {
        atomicAdd(&g_s1[tid * SPAD], sS[tid]);
        atomicAdd(&g_q1[tid * SPAD], sQ[tid]);
    }
}

// ---------------- K4: streaming BN1+ReLU masked-mean -> agg2 ----------------
// 256 thr = 8 warps, one node per warp; predicates computed before row loads (MLP=9)
__global__ void k_bnagg(const float* __restrict__ node_ts,
                        const float* __restrict__ nbt,
                        const float* __restrict__ g1, const float* __restrict__ be1) {
    __shared__ float sSc[HID], sSh[HID];
    const int tid = threadIdx.x;
    if (tid < HID) {
        const float mean = g_s1[tid * SPAD] * (1.f / (float)M_ROWS);
        const float var  = g_q1[tid * SPAD] * (1.f / (float)M_ROWS) - mean * mean;
        const float sc   = __ldg(&g1[tid]) * rsqrtf(fmaxf(var, 0.f) + EPS);
        sSc[tid] = sc;
        sSh[tid] = __ldg(&be1[tid]) - mean * sc;
    }
    __syncthreads();
    const int w = tid >> 5, lane = tid & 31;
    const int i = blockIdx.x * 8 + w;
    const float ts = __ldg(&node_ts[i]);
    // all validity predicates first: independent loads, batched issue
    bool val[D];
    int cnt = 1;
#pragma unroll
    for (int j = 0; j < D; j++) {
        val[j] = (__ldg(&nbt[i * D + j]) <= ts);
        cnt += val[j] ? 1 : 0;
    }
    const float4 sc4 = *(const float4*)&sSc[lane * 4];
    const float4 sh4 = *(const float4*)&sSh[lane * 4];
    // self row (always valid) + 8 predicated row loads, all independent
    float4 v = *(const float4*)&g_pre1[(size_t)(i * DP1 + D) * HID + lane * 4];
    float4 acc;
    acc.x = fmaxf(fmaf(v.x, sc4.x, sh4.x), 0.f);
    acc.y = fmaxf(fmaf(v.y, sc4.y, sh4.y), 0.f);
    acc.z = fmaxf(fmaf(v.z, sc4.z, sh4.z), 0.f);
    acc.w = fmaxf(fmaf(v.w, sc4.w, sh4.w), 0.f);
#pragma unroll
    for (int j = 0; j < D; j++) {
        if (val[j]) {
            const float4 u = *(const float4*)&g_pre1[(size_t)(i * DP1 + j) * HID + lane * 4];
            acc.x += fmaxf(fmaf(u.x, sc4.x, sh4.x), 0.f);
            acc.y += fmaxf(fmaf(u.y, sc4.y, sh4.y), 0.f);
            acc.z += fmaxf(fmaf(u.z, sc4.z, sh4.z), 0.f);
            acc.w += fmaxf(fmaf(u.w, sc4.w, sh4.w), 0.f);
        }
    }
    const float inv = 1.f / (float)cnt;
    float4 o = make_float4(acc.x * inv, acc.y * inv, acc.z * inv, acc.w * inv);
    *(float4*)&g_agg2[(size_t)i * HID + lane * 4] = o;
}

// ---------------- K5: pre2 = agg2 @ W2 + b2, + BN2 stat partials ----------------
// 256 thr, 32 rows/block; thread tile 2 rows x 4 cols
__global__ void k_gemm2(const float* __restrict__ W2, const float* __restrict__ b2) {
    __shared__ float sA[32 * HID];      // 16 KB
    __shared__ float sW[HID * OUT_F];   // 32 KB
    __shared__ float sS[OUT_F], sQ[OUT_F];
    const int tid  = threadIdx.x;
    const int row0 = blockIdx.x * 32;
    for (int i = tid; i < 32 * HID; i += 256) sA[i] = g_agg2[(size_t)row0 * HID + i];
    for (int i = tid; i < HID * OUT_F; i += 256) sW[i] = W2[i];
    if (tid < OUT_F) { sS[tid] = 0.f; sQ[tid] = 0.f; }
    __syncthreads();
    const int tr = tid >> 4;   // 0..15 -> rows tr*2
    const int tc = tid & 15;   // cols tc*4
    float acc[2][4];
#pragma unroll
    for (int r = 0; r < 2; r++)
#pragma unroll
        for (int cc = 0; cc < 4; cc++) acc[r][cc] = 0.f;
#pragma unroll 8
    for (int f = 0; f < HID; f++) {
        const float4 wv = *(const float4*)&sW[f * OUT_F + tc * 4];
#pragma unroll
        for (int r = 0; r < 2; r++) {
            const float a = sA[(tr * 2 + r) * HID + f];
            acc[r][0] = fmaf(a, wv.x, acc[r][0]);
            acc[r][1] = fmaf(a, wv.y, acc[r][1]);
            acc[r][2] = fmaf(a, wv.z, acc[r][2]);
            acc[r][3] = fmaf(a, wv.w, acc[r][3]);
        }
    }
    const float4 bbv = *(const float4*)&b2[tc * 4];
    float ps[4] = {0.f, 0.f, 0.f, 0.f}, pq[4] = {0.f, 0.f, 0.f, 0.f};
#pragma unroll
    for (int r = 0; r < 2; r++) {
        float4 o = make_float4(acc[r][0] + bbv.x, acc[r][1] + bbv.y,
                               acc[r][2] + bbv.z, acc[r][3] + bbv.w);
        *(float4*)&g_pre2[(size_t)(row0 + tr * 2 + r) * OUT_F + tc * 4] = o;
        ps[0] += o.x; ps[1] += o.y; ps[2] += o.z; ps[3] += o.w;
        pq[0] += o.x * o.x; pq[1] += o.y * o.y; pq[2] += o.z * o.z; pq[3] += o.w * o.w;
    }
#pragma unroll
    for (int cc = 0; cc < 4; cc++) {
        atomicAdd(&sS[tc * 4 + cc], ps[cc]);
        atomicAdd(&sQ[tc * 4 + cc], pq[cc]);
    }
    __syncthreads();
    if (tid < OUT_F) {
        atomicAdd(&g_s2[tid * SPAD], sS[tid]);
        atomicAdd(&g_q2[tid * SPAD], sQ[tid]);
    }
}

// ---------------- K6: decoder + BCE loss with fused BN2+ReLU (+ last-block finalize) ----------------
// 256 thr = 8 warps; 2 pairs/warp (half-warp float4 dot); 128 pairs/block
__global__ void k_loss(const int* __restrict__ target, const int* __restrict__ neg,
                       const float* __restrict__ g2, const float* __restrict__ be2,
                       const float* __restrict__ Wd, const float* __restrict__ bd,
                       float* __restrict__ out) {
    __shared__ float  sWd[OUT_F], sSc[OUT_F], sSh[OUT_F];
    __shared__ double sAcc[8];
    const int tid = threadIdx.x, w = tid >> 5, lane = tid & 31;
    const int half = lane >> 4, hl = lane & 15;
    if (tid < OUT_F) {
        sWd[tid] = Wd[tid];
        const float mean = g_s2[tid * SPAD] * (1.f / (float)N_NODES);
        const float var  = g_q2[tid * SPAD] * (1.f / (float)N_NODES) - mean * mean;
        const float sc   = __ldg(&g2[tid]) * rsqrtf(fmaxf(var, 0.f) + EPS);
        sSc[tid] = sc;
        sSh[tid] = __ldg(&be2[tid]) - mean * sc;
    }
    __syncthreads();
    const float bdv = __ldg(&bd[0]);
    const float4 wd  = *(const float4*)&sWd[hl * 4];
    const float4 sc4 = *(const float4*)&sSc[hl * 4];
    const float4 sh4 = *(const float4*)&sSh[hl * 4];
    double acc = 0.0;
    const int p0 = blockIdx.x * 128;
    for (int it = 0; it < 8; it++) {
        const int p = p0 + it * 16 + w * 2 + half;
        float d = 0.f; float label = 0.f; bool live = (p < 2 * NE);
        if (live) {
            int a, b;
            if (p < NE) { a = __ldg(&target[p]);   b = __ldg(&target[NE + p]); label = 1.f; }
            else        { a = __ldg(&neg[p - NE]); b = __ldg(&neg[p]);         label = 0.f; }
            float4 va = *(const float4*)&g_pre2[(size_t)a * OUT_F + hl * 4];
            float4 vb = *(const float4*)&g_pre2[(size_t)b * OUT_F + hl * 4];
            float4 ea, eb;
            ea.x = fmaxf(fmaf(va.x, sc4.x, sh4.x), 0.f);
            ea.y = fmaxf(fmaf(va.y, sc4.y, sh4.y), 0.f);
            ea.z = fmaxf(fmaf(va.z, sc4.z, sh4.z), 0.f);
            ea.w = fmaxf(fmaf(va.w, sc4.w, sh4.w), 0.f);
            eb.x = fmaxf(fmaf(vb.x, sc4.x, sh4.x), 0.f);
            eb.y = fmaxf(fmaf(vb.y, sc4.y, sh4.y), 0.f);
            eb.z = fmaxf(fmaf(vb.z, sc4.z, sh4.z), 0.f);
            eb.w = fmaxf(fmaf(vb.w, sc4.w, sh4.w), 0.f);
            d = ea.x * eb.x * wd.x + ea.y * eb.y * wd.y
              + ea.z * eb.z * wd.z + ea.w * eb.w * wd.w;
        }
#pragma unroll
        for (int off = 8; off; off >>= 1) d += __shfl_xor_sync(0xffffffff, d, off);
        if (hl == 0 && live) {
            const float pl   = d + bdv;
            const float term = fmaxf(pl, 0.f) - pl * label + log1pf(expf(-fabsf(pl)));
            acc += (double)term;
        }
    }
    acc += __shfl_xor_sync(0xffffffff, acc, 16);
    if (lane == 0) sAcc[w] = acc;
    __syncthreads();
    if (tid == 0) {
        double s = 0.0;
#pragma unroll
        for (int k = 0; k < 8; k++) s += sAcc[k];
        atomicAdd(&g_loss, s);
        __threadfence();
        const int dn = atomicAdd(&g_done, 1);
        if (dn == (int)gridDim.x - 1)
            out[0] = (float)(g_loss * (1.0 / (2.0 * (double)NE)));
    }
}

// ---------------- launch ----------------
extern "C" void kernel_launch(void* const* d_in, const int* in_sizes, int n_in,
                              void* d_out, int out_size) {
    const float* x       = (const float*)d_in[0];
    const float* node_ts = (const float*)d_in[1];
    const int*   nbi     = (const int*)  d_in[2];
    const float* nbt     = (const float*)d_in[3];
    const int*   target  = (const int*)  d_in[4];
    const int*   neg     = (const int*)  d_in[5];
    const float* W1      = (const float*)d_in[6];
    const float* b1      = (const float*)d_in[7];
    const float* g1      = (const float*)d_in[8];
    const float* be1     = (const float*)d_in[9];
    const float* W2      = (const float*)d_in[10];
    const float* b2      = (const float*)d_in[11];
    const float* g2      = (const float*)d_in[12];
    const float* be2     = (const float*)d_in[13];
    const float* Wd      = (const float*)d_in[14];
    const float* bd      = (const float*)d_in[15];
    float* out = (float*)d_out;

    k_gemm1 <<<N_NODES / 32, 128>>>(x, W1);
    k_build <<<(M_ROWS + 255) / 256, 256>>>(node_ts, nbi, nbt);
    k_child <<<N_NODES / 4, 128>>>(nbi, nbt, b1);
    k_bnagg <<<N_NODES / 8, 256>>>(node_ts, nbt, g1, be1);
    k_gemm2 <<<N_NODES / 32, 256>>>(W2, b2);
    k_loss  <<<(2 * NE + 127) / 128, 256>>>(target, neg, g2, be2, Wd, bd, out);
}

// round 7
// speedup vs baseline: 1.5335x; 1.1070x over previous
#include <cuda_runtime.h>
#include <cuda_fp16.h>
#include <math.h>

#define N_NODES 20000
#define D 8
#define DP1 9
#define M_ROWS (N_NODES * DP1)   // 180000
#define IN_F 64
#define HID 128
#define OUT_F 64
#define NE 100000
#define EPS 1e-5f
#define SPAD 64
#define CAP 96

// ---------------- scratch ----------------
__device__ float  g_y1[N_NODES * HID];        // x @ W1  (10.24 MB)
__device__ __half g_pre1h[M_ROWS * HID];      // fp16 pre1 (46 MB)
__device__ float  g_pre2[N_NODES * OUT_F];
__device__ int    g_cnt[N_NODES];
__device__ float  g_bq[N_NODES * CAP];
__device__ int    g_bm[N_NODES * CAP];
__device__ float  g_s1[HID * SPAD],  g_q1[HID * SPAD];
__device__ float  g_s2[OUT_F * SPAD], g_q2[OUT_F * SPAD];
__device__ double g_loss;
__device__ int    g_done;

// ---------------- K1: y1 = x @ W1 (+ per-replay zeroing) ----------------
__global__ void k_gemm1(const float* __restrict__ x, const float* __restrict__ W1) {
    __shared__ float sX[32 * IN_F];
    __shared__ float sW[IN_F * HID];
    const int tid  = threadIdx.x;
    const int row0 = blockIdx.x * 32;
    if (tid < 32) g_cnt[blockIdx.x * 32 + tid] = 0;
    if (blockIdx.x == 0) {
        if (tid < HID)   { g_s1[tid * SPAD] = 0.f; g_q1[tid * SPAD] = 0.f; }
        if (tid < OUT_F) { g_s2[tid * SPAD] = 0.f; g_q2[tid * SPAD] = 0.f; }
        if (tid == 0)    { g_loss = 0.0; g_done = 0; }
    }
    for (int i = tid; i < 32 * IN_F; i += 128) sX[i] = x[(size_t)row0 * IN_F + i];
    for (int i = tid; i < IN_F * HID; i += 128) sW[i] = W1[i];
    __syncthreads();
    const int tr = tid >> 5;
    const int tc = tid & 31;
    float acc[8][4];
#pragma unroll
    for (int r = 0; r < 8; r++)
#pragma unroll
        for (int c = 0; c < 4; c++) acc[r][c] = 0.f;
#pragma unroll 8
    for (int f = 0; f < IN_F; f++) {
        const float4 w = *(const float4*)&sW[f * HID + tc * 4];
#pragma unroll
        for (int r = 0; r < 8; r++) {
            const float a = sX[(tr * 8 + r) * IN_F + f];
            acc[r][0] = fmaf(a, w.x, acc[r][0]);
            acc[r][1] = fmaf(a, w.y, acc[r][1]);
            acc[r][2] = fmaf(a, w.z, acc[r][2]);
            acc[r][3] = fmaf(a, w.w, acc[r][3]);
        }
    }
#pragma unroll
    for (int r = 0; r < 8; r++) {
        float4 v = make_float4(acc[r][0], acc[r][1], acc[r][2], acc[r][3]);
        *(float4*)&g_y1[(size_t)(row0 + tr * 8 + r) * HID + tc * 4] = v;
    }
}

// ---------------- K2: scatter queries into per-child buckets ----------------
__global__ void k_build(const float* __restrict__ node_ts,
                        const int*   __restrict__ nbi,
                        const float* __restrict__ nbt) {
    const int q = blockIdx.x * blockDim.x + threadIdx.x;
    if (q >= M_ROWS) return;
    const int i = q / DP1;
    const int j = q - i * DP1;
    const float ts_i = __ldg(&node_ts[i]);
    int ci; float cts;
    if (j < D) { ci = __ldg(&nbi[i * D + j]); cts = __ldg(&nbt[i * D + j]); }
    else       { ci = i;                      cts = ts_i; }
    const bool valid = (cts <= ts_i);
    const int slot = atomicAdd(&g_cnt[ci], 1);
    if (slot < CAP) {
        g_bq[ci * CAP + slot] = cts;
        g_bm[ci * CAP + slot] = valid ? q : (q | 0x80000000);
    }
}

// ---------------- K3: per-child worker (8 warps/block) ----------------
__global__ void k_child(const int*   __restrict__ nbi,
                        const float* __restrict__ nbt,
                        const float* __restrict__ b1) {
    __shared__ float sS[HID];
    __shared__ float sQ[HID];
    const int tid  = threadIdx.x;
    const int w    = tid >> 5, lane = tid & 31;
    if (tid < HID)            sS[tid] = 0.f;
    else if (tid < 2 * HID)   sQ[tid - HID] = 0.f;
    __syncthreads();
    const int c = blockIdx.x * 8 + w;

    float ts[D];
#pragma unroll
    for (int k = 0; k < D; k++) ts[k] = __ldg(&nbt[c * D + k]);

    const float4 self = *(const float4*)&g_y1[(size_t)c * HID + lane * 4];
    float4 row[D];
#pragma unroll
    for (int k = 0; k < D; k++) {
        const int gi = __ldg(&nbi[c * D + k]);
        row[k] = *(const float4*)&g_y1[(size_t)gi * HID + lane * 4];
    }
    const float4 bb = *(const float4*)&b1[lane * 4];

    const int n = min(g_cnt[c], CAP);
    float4 ps = make_float4(0.f, 0.f, 0.f, 0.f);
    float4 pq = make_float4(0.f, 0.f, 0.f, 0.f);
    for (int s = 0; s < n; s++) {
        const float cts = g_bq[c * CAP + s];      // uniform across warp
        const int   me  = g_bm[c * CAP + s];
        float4 acc = self; int cnt = 1;
#pragma unroll
        for (int k = 0; k < D; k++) {
            if (ts[k] <= cts) {                   // uniform register predicate
                acc.x += row[k].x; acc.y += row[k].y;
                acc.z += row[k].z; acc.w += row[k].w;
                cnt++;
            }
        }
        const float inv = 1.f / (float)cnt;
        float4 o;
        o.x = fmaf(acc.x, inv, bb.x);
        o.y = fmaf(acc.y, inv, bb.y);
        o.z = fmaf(acc.z, inv, bb.z);
        o.w = fmaf(acc.w, inv, bb.w);
        ps.x += o.x; ps.y += o.y; ps.z += o.z; ps.w += o.w;
        pq.x += o.x * o.x; pq.y += o.y * o.y; pq.z += o.z * o.z; pq.w += o.w * o.w;
        if (me >= 0) {                            // store only mask2-valid rows (fp16)
            union { __half2 h[2]; uint2 u; } pk;
            pk.h[0] = __floats2half2_rn(o.x, o.y);
            pk.h[1] = __floats2half2_rn(o.z, o.w);
            *(uint2*)&g_pre1h[(size_t)me * HID + lane * 4] = pk.u;
        }
    }
    atomicAdd(&sS[lane * 4 + 0], ps.x);
    atomicAdd(&sS[lane * 4 + 1], ps.y);
    atomicAdd(&sS[lane * 4 + 2], ps.z);
    atomicAdd(&sS[lane * 4 + 3], ps.w);
    atomicAdd(&sQ[lane * 4 + 0], pq.x);
    atomicAdd(&sQ[lane * 4 + 1], pq.y);
    atomicAdd(&sQ[lane * 4 + 2], pq.z);
    atomicAdd(&sQ[lane * 4 + 3], pq.w);
    __syncthreads();
    if (tid < HID) {
        atomicAdd(&g_s1[tid * SPAD], sS[tid]);
        atomicAdd(&g_q1[tid * SPAD], sQ[tid]);
    }
}

// ---------------- K4: fused BN1+ReLU masked-mean -> gemm2 + BN2 partials ----------------
// 256 thr = 8 warps; 32 nodes/block (4 per warp in phase A); grid 625
__global__ void k_bngemm2(const float* __restrict__ node_ts,
                          const float* __restrict__ nbt,
                          const float* __restrict__ g1, const float* __restrict__ be1,
                          const float* __restrict__ W2, const float* __restrict__ b2) {
    __shared__ float sA[32 * HID];      // 16 KB (agg2 tile)
    __shared__ float sW[HID * OUT_F];   // 32 KB
    __shared__ float sSc[HID], sSh[HID];
    __shared__ float sS[OUT_F], sQ[OUT_F];
    const int tid  = threadIdx.x;
    const int w    = tid >> 5, lane = tid & 31;
    const int row0 = blockIdx.x * 32;
    for (int i = tid; i < HID * OUT_F; i += 256) sW[i] = W2[i];
    if (tid < HID) {
        const float mean = g_s1[tid * SPAD] * (1.f / (float)M_ROWS);
        const float var  = g_q1[tid * SPAD] * (1.f / (float)M_ROWS) - mean * mean;
        const float sc   = __ldg(&g1[tid]) * rsqrtf(fmaxf(var, 0.f) + EPS);
        sSc[tid] = sc;
        sSh[tid] = __ldg(&be1[tid]) - mean * sc;
    }
    if (tid < OUT_F) { sS[tid] = 0.f; sQ[tid] = 0.f; }
    __syncthreads();
    const float4 sc4 = *(const float4*)&sSc[lane * 4];
    const float4 sh4 = *(const float4*)&sSh[lane * 4];
    // ---- phase A: each warp computes 4 nodes' agg2 rows ----
    for (int u = 0; u < 4; u++) {
        const int i  = row0 + w * 4 + u;
        const float ts = __ldg(&node_ts[i]);
        bool val[D]; int cnt = 1;
#pragma unroll
        for (int j = 0; j < D; j++) {
            val[j] = (__ldg(&nbt[i * D + j]) <= ts);
            cnt += val[j] ? 1 : 0;
        }
        // self row + predicated fp16 row loads, all independent
        uint2 us = *(const uint2*)&g_pre1h[(size_t)(i * DP1 + D) * HID + lane * 4];
        float2 f0 = __half22float2(*(__half2*)&us.x);
        float2 f1 = __half22float2(*(__half2*)&us.y);
        float4 acc;
        acc.x = fmaxf(fmaf(f0.x, sc4.x, sh4.x), 0.f);
        acc.y = fmaxf(fmaf(f0.y, sc4.y, sh4.y), 0.f);
        acc.z = fmaxf(fmaf(f1.x, sc4.z, sh4.z), 0.f);
        acc.w = fmaxf(fmaf(f1.y, sc4.w, sh4.w), 0.f);
#pragma unroll
        for (int j = 0; j < D; j++) {
            if (val[j]) {
                uint2 uu = *(const uint2*)&g_pre1h[(size_t)(i * DP1 + j) * HID + lane * 4];
                float2 a0 = __half22float2(*(__half2*)&uu.x);
                float2 a1 = __half22float2(*(__half2*)&uu.y);
                acc.x += fmaxf(fmaf(a0.x, sc4.x, sh4.x), 0.f);
                acc.y += fmaxf(fmaf(a0.y, sc4.y, sh4.y), 0.f);
                acc.z += fmaxf(fmaf(a1.x, sc4.z, sh4.z), 0.f);
                acc.w += fmaxf(fmaf(a1.y, sc4.w, sh4.w), 0.f);
            }
        }
        const float inv = 1.f / (float)cnt;
        float4 o = make_float4(acc.x * inv, acc.y * inv, acc.z * inv, acc.w * inv);
        *(float4*)&sA[(w * 4 + u) * HID + lane * 4] = o;
    }
    __syncthreads();
    // ---- phase B: [32 x 128] @ [128 x 64] ----
    const int tr = tid >> 4;   // rows tr*2
    const int tc = tid & 15;   // cols tc*4
    float acc[2][4];
#pragma unroll
    for (int r = 0; r < 2; r++)
#pragma unroll
        for (int cc = 0; cc < 4; cc++) acc[r][cc] = 0.f;
#pragma unroll 8
    for (int f = 0; f < HID; f++) {
        const float4 wv = *(const float4*)&sW[f * OUT_F + tc * 4];
#pragma unroll
        for (int r = 0; r < 2; r++) {
            const float a = sA[(tr * 2 + r) * HID + f];
            acc[r][0] = fmaf(a, wv.x, acc[r][0]);
            acc[r][1] = fmaf(a, wv.y, acc[r][1]);
            acc[r][2] = fmaf(a, wv.z, acc[r][2]);
            acc[r][3] = fmaf(a, wv.w, acc[r][3]);
        }
    }
    const float4 bbv = *(const float4*)&b2[tc * 4];
    float ps[4] = {0.f, 0.f, 0.f, 0.f}, pq[4] = {0.f, 0.f, 0.f, 0.f};
#pragma unroll
    for (int r = 0; r < 2; r++) {
        float4 o = make_float4(acc[r][0] + bbv.x, acc[r][1] + bbv.y,
                               acc[r][2] + bbv.z, acc[r][3] + bbv.w);
        *(float4*)&g_pre2[(size_t)(row0 + tr * 2 + r) * OUT_F + tc * 4] = o;
        ps[0] += o.x; ps[1] += o.y; ps[2] += o.z; ps[3] += o.w;
        pq[0] += o.x * o.x; pq[1] += o.y * o.y; pq[2] += o.z * o.z; pq[3] += o.w * o.w;
    }
#pragma unroll
    for (int cc = 0; cc < 4; cc++) {
        atomicAdd(&sS[tc * 4 + cc], ps[cc]);
        atomicAdd(&sQ[tc * 4 + cc], pq[cc]);
    }
    __syncthreads();
    if (tid < OUT_F) {
        atomicAdd(&g_s2[tid * SPAD], sS[tid]);
        atomicAdd(&g_q2[tid * SPAD], sQ[tid]);
    }
}

// ---------------- K5: decoder + BCE with fused BN2+ReLU ----------------
// 256 thr = 8 warps; 4 pairs/warp (8-lane groups, 2x float4 per lane); 256 pairs/block
__global__ void k_loss(const int* __restrict__ target, const int* __restrict__ neg,
                       const float* __restrict__ g2, const float* __restrict__ be2,
                       const float* __restrict__ Wd, const float* __restrict__ bd,
                       float* __restrict__ out) {
    __shared__ float  sWd[OUT_F], sSc[OUT_F], sSh[OUT_F];
    __shared__ double sAcc[8];
    const int tid = threadIdx.x, w = tid >> 5, lane = tid & 31;
    const int grp = lane >> 3, hl = lane & 7;
    if (tid < OUT_F) {
        sWd[tid] = Wd[tid];
        const float mean = g_s2[tid * SPAD] * (1.f / (float)N_NODES);
        const float var  = g_q2[tid * SPAD] * (1.f / (float)N_NODES) - mean * mean;
        const float sc   = __ldg(&g2[tid]) * rsqrtf(fmaxf(var, 0.f) + EPS);
        sSc[tid] = sc;
        sSh[tid] = __ldg(&be2[tid]) - mean * sc;
    }
    __syncthreads();
    const float bdv = __ldg(&bd[0]);
    const float4 wd0  = *(const float4*)&sWd[hl * 8];
    const float4 wd1  = *(const float4*)&sWd[hl * 8 + 4];
    const float4 sca  = *(const float4*)&sSc[hl * 8];
    const float4 scb  = *(const float4*)&sSc[hl * 8 + 4];
    const float4 sha  = *(const float4*)&sSh[hl * 8];
    const float4 shb  = *(const float4*)&sSh[hl * 8 + 4];
    double acc = 0.0;
    const int p0 = blockIdx.x * 256;
    for (int it = 0; it < 8; it++) {
        const int p = p0 + it * 32 + w * 4 + grp;
        float d = 0.f; float label = 0.f; bool live = (p < 2 * NE);
        if (live) {
            int a, b;
            if (p < NE) { a = __ldg(&target[p]);   b = __ldg(&target[NE + p]); label = 1.f; }
            else        { a = __ldg(&neg[p - NE]); b = __ldg(&neg[p]);         label = 0.f; }
            const float4 va0 = *(const float4*)&g_pre2[(size_t)a * OUT_F + hl * 8];
            const float4 va1 = *(const float4*)&g_pre2[(size_t)a * OUT_F + hl * 8 + 4];
            const float4 vb0 = *(const float4*)&g_pre2[(size_t)b * OUT_F + hl * 8];
            const float4 vb1 = *(const float4*)&g_pre2[(size_t)b * OUT_F + hl * 8 + 4];
            float4 ea0, ea1, eb0, eb1;
            ea0.x = fmaxf(fmaf(va0.x, sca.x, sha.x), 0.f);
            ea0.y = fmaxf(fmaf(va0.y, sca.y, sha.y), 0.f);
            ea0.z = fmaxf(fmaf(va0.z, sca.z, sha.z), 0.f);
            ea0.w = fmaxf(fmaf(va0.w, sca.w, sha.w), 0.f);
            ea1.x = fmaxf(fmaf(va1.x, scb.x, shb.x), 0.f);
            ea1.y = fmaxf(fmaf(va1.y, scb.y, shb.y), 0.f);
            ea1.z = fmaxf(fmaf(va1.z, scb.z, shb.z), 0.f);
            ea1.w = fmaxf(fmaf(va1.w, scb.w, shb.w), 0.f);
            eb0.x = fmaxf(fmaf(vb0.x, sca.x, sha.x), 0.f);
            eb0.y = fmaxf(fmaf(vb0.y, sca.y, sha.y), 0.f);
            eb0.z = fmaxf(fmaf(vb0.z, sca.z, sha.z), 0.f);
            eb0.w = fmaxf(fmaf(vb0.w, sca.w, sha.w), 0.f);
            eb1.x = fmaxf(fmaf(vb1.x, scb.x, shb.x), 0.f);
            eb1.y = fmaxf(fmaf(vb1.y, scb.y, shb.y), 0.f);
            eb1.z = fmaxf(fmaf(vb1.z, scb.z, shb.z), 0.f);
            eb1.w = fmaxf(fmaf(vb1.w, scb.w, shb.w), 0.f);
            d = ea0.x * eb0.x * wd0.x + ea0.y * eb0.y * wd0.y
              + ea0.z * eb0.z * wd0.z + ea0.w * eb0.w * wd0.w
              + ea1.x * eb1.x * wd1.x + ea1.y * eb1.y * wd1.y
              + ea1.z * eb1.z * wd1.z + ea1.w * eb1.w * wd1.w;
        }
#pragma unroll
        for (int off = 4; off; off >>= 1) d += __shfl_xor_sync(0xffffffff, d, off);
        if (hl == 0 && live) {
            const float pl   = d + bdv;
            const float term = fmaxf(pl, 0.f) - pl * label + log1pf(__expf(-fabsf(pl)));
            acc += (double)term;
        }
    }
    // reduce lanes 0,8,16,24
    acc += __shfl_xor_sync(0xffffffff, acc, 8);
    acc += __shfl_xor_sync(0xffffffff, acc, 16);
    if (lane == 0) sAcc[w] = acc;
    __syncthreads();
    if (tid == 0) {
        double s = 0.0;
#pragma unroll
        for (int k = 0; k < 8; k++) s += sAcc[k];
        atomicAdd(&g_loss, s);
        __threadfence();
        const int dn = atomicAdd(&g_done, 1);
        if (dn == (int)gridDim.x - 1)
            out[0] = (float)(g_loss * (1.0 / (2.0 * (double)NE)));
    }
}

// ---------------- launch ----------------
extern "C" void kernel_launch(void* const* d_in, const int* in_sizes, int n_in,
                              void* d_out, int out_size) {
    const float* x       = (const float*)d_in[0];
    const float* node_ts = (const float*)d_in[1];
    const int*   nbi     = (const int*)  d_in[2];
    const float* nbt     = (const float*)d_in[3];
    const int*   target  = (const int*)  d_in[4];
    const int*   neg     = (const int*)  d_in[5];
    const float* W1      = (const float*)d_in[6];
    const float* b1      = (const float*)d_in[7];
    const float* g1      = (const float*)d_in[8];
    const float* be1     = (const float*)d_in[9];
    const float* W2      = (const float*)d_in[10];
    const float* b2      = (const float*)d_in[11];
    const float* g2      = (const float*)d_in[12];
    const float* be2     = (const float*)d_in[13];
    const float* Wd      = (const float*)d_in[14];
    const float* bd      = (const float*)d_in[15];
    float* out = (float*)d_out;

    k_gemm1  <<<N_NODES / 32, 128>>>(x, W1);
    k_build  <<<(M_ROWS + 255) / 256, 256>>>(node_ts, nbi, nbt);
    k_child  <<<N_NODES / 8, 256>>>(nbi, nbt, b1);
    k_bngemm2<<<N_NODES / 32, 256>>>(node_ts, nbt, g1, be1, W2, b2);
    k_loss   <<<(2 * NE + 255) / 256, 256>>>(target, neg, g2, be2, Wd, bd, out);
}